// round 12
// baseline (speedup 1.0000x reference)
#include <cuda_runtime.h>
#include <cuda_fp16.h>
#include <cstdint>

static constexpr int KDIM = 4096;
static constexpr int NDIM = 4096;
static constexpr int BDIM = 8192;
static constexpr int BK   = 64;
static constexpr int NCH  = KDIM / BK;                 // 64 chunks
static constexpr int STAGE_A = 0;
static constexpr int STAGE_W = 16384;
static constexpr int STAGE_BYTES = 32768;
static constexpr int NSTAGE = 3;
static constexpr int OFF_BS  = NSTAGE * STAGE_BYTES;   // 98304
static constexpr int OFF_GW  = OFF_BS + 512;
static constexpr int OFF_GB  = OFF_GW + 512;
static constexpr int OFF_RED = OFF_GB + 512;           // float2[128][4] = 4096
static constexpr int SMEM_BYTES = OFF_RED + 4096;      // 104448 -> 2 CTAs/SM

__device__ __align__(16) __half g_xh[(size_t)BDIM * KDIM];   // 64 MB
__device__ __align__(16) __half g_wh[(size_t)NDIM * KDIM];   // 32 MB

#define DINL __device__ __forceinline__

DINL uint32_t smem_u32(const void* p) {
    uint32_t a;
    asm("{ .reg .u64 t; cvta.to.shared.u64 t, %1; cvt.u32.u64 %0, t; }" : "=r"(a) : "l"(p));
    return a;
}
DINL void cp_async16(uint32_t s, const void* g) {
    asm volatile("cp.async.cg.shared.global [%0], [%1], 16;" :: "r"(s), "l"(g) : "memory");
}
DINL void cp_commit() { asm volatile("cp.async.commit_group;" ::: "memory"); }
template <int N> DINL void cp_wait() { asm volatile("cp.async.wait_group %0;" :: "n"(N) : "memory"); }

#define LDMX4(d, addr)                                                              \
    asm volatile("ldmatrix.sync.aligned.m8n8.x4.shared.b16 {%0,%1,%2,%3}, [%4];"    \
        : "=r"((d)[0]), "=r"((d)[1]), "=r"((d)[2]), "=r"((d)[3]) : "r"(addr))

#define MMA16816(c, a, b0, b1)                                                      \
    asm volatile("mma.sync.aligned.m16n8k16.row.col.f32.f16.f16.f32 "               \
        "{%0,%1,%2,%3}, {%4,%5,%6,%7}, {%8,%9}, {%0,%1,%2,%3};"                     \
        : "+f"((c)[0]), "+f"((c)[1]), "+f"((c)[2]), "+f"((c)[3])                    \
        : "r"((a)[0]), "r"((a)[1]), "r"((a)[2]), "r"((a)[3]), "r"(b0), "r"(b1))

// ---------------- fp32 -> fp16 pre-convert (both tensors, one launch) ----------------
static constexpr int XBLK = (int)((size_t)BDIM * KDIM / 2048);   // 16384
static constexpr int WBLK = (int)((size_t)NDIM * KDIM / 2048);   // 8192

__global__ void __launch_bounds__(256) cvt2_kernel(const float* __restrict__ x,
                                                   const float* __restrict__ w,
                                                   __half* __restrict__ xh,
                                                   __half* __restrict__ wh) {
    int b = blockIdx.x;
    const float* src; __half* dst;
    size_t base;
    if (b < XBLK) { src = x; dst = xh; base = (size_t)b * 2048; }
    else          { src = w; dst = wh; base = (size_t)(b - XBLK) * 2048; }
    size_t i = base + (size_t)threadIdx.x * 8;
    float4 f0 = *(const float4*)(src + i);
    float4 f1 = *(const float4*)(src + i + 4);
    __half2 h0 = __floats2half2_rn(f0.x, f0.y);
    __half2 h1 = __floats2half2_rn(f0.z, f0.w);
    __half2 h2 = __floats2half2_rn(f1.x, f1.y);
    __half2 h3 = __floats2half2_rn(f1.z, f1.w);
    uint4 v = {*(uint32_t*)&h0, *(uint32_t*)&h1, *(uint32_t*)&h2, *(uint32_t*)&h3};
    *(uint4*)(dst + i) = v;
}

// ---------------- fused GEMM + bias + hardtanh + mish + GroupNorm ----------------
// 256 threads, 8 warps, 64x32 warp tiles, 2 CTAs/SM (reg cap 128)
__global__ void __launch_bounds__(256, 2)
fused_gemm_mish_gn(const float* __restrict__ bl, const float* __restrict__ be,
                   const float* __restrict__ gwp, const float* __restrict__ gbp,
                   float* __restrict__ out) {
    extern __shared__ __align__(16) unsigned char sm[];
    const uint32_t sb = smem_u32(sm);

    const int tid  = threadIdx.x;
    const int lane = tid & 31;
    const int wid  = tid >> 5;        // 8 warps
    const int wm   = wid & 1;         // 2 row-blocks of 64
    const int wn   = wid >> 1;        // 4 col-blocks of 32
    const int m0   = blockIdx.y << 7;
    const int n0   = blockIdx.x << 7;

    float* bs  = (float*)(sm + OFF_BS);
    float* gws = (float*)(sm + OFF_GW);
    float* gbs = (float*)(sm + OFF_GB);
    float2* red = (float2*)(sm + OFF_RED);

    if (tid < 128) {
        bs[tid]  = bl[n0 + tid] + be[n0 + tid];
        gws[tid] = gwp[n0 + tid];
        gbs[tid] = gbp[n0 + tid];
    }

    // ---- cp.async mapping: thread t -> row t>>1, four 16B chunks (t&1)*4+0..3 ----
    const int ldr = tid >> 1, ldc = (tid & 1) * 4;
    const __half* a_g = g_xh + (size_t)(m0 + ldr) * KDIM + ldc * 8;
    const __half* w_g = g_wh + (size_t)(n0 + ldr) * KDIM + ldc * 8;
    const uint32_t sts_a = sb + STAGE_A + (uint32_t)ldr * 128;
    const uint32_t sts_w = sb + STAGE_W + (uint32_t)ldr * 128;
    uint32_t swz[4];
#pragma unroll
    for (int j = 0; j < 4; ++j) swz[j] = (uint32_t)((ldc + j) ^ (ldr & 7)) * 16;

    auto issue_chunk = [&](int kc, int st) {
        uint32_t so = (uint32_t)st * STAGE_BYTES;
        const __half* ga = a_g + kc * BK;
        const __half* gw = w_g + kc * BK;
#pragma unroll
        for (int j = 0; j < 4; ++j) {
            cp_async16(sts_a + so + swz[j], ga + j * 8);
            cp_async16(sts_w + so + swz[j], gw + j * 8);
        }
        cp_commit();
    };

    float acc[4][4][4];
#pragma unroll
    for (int i = 0; i < 4; ++i)
#pragma unroll
        for (int j = 0; j < 4; ++j)
#pragma unroll
            for (int k = 0; k < 4; ++k) acc[i][j][k] = 0.f;

    const uint32_t a_row = sb + STAGE_A + (uint32_t)(wm * 64 + (lane & 15)) * 128;
    const uint32_t w_row = sb + STAGE_W + (uint32_t)(wn * 32 + (lane & 15)) * 128;
    const int lhalf = lane >> 4;
    const int lxor  = lane & 7;

    // JIT-af variant: bf once per kt, af loaded immediately before its 4 MMAs.
    auto do_mma = [&](int st) {
        uint32_t so = (uint32_t)st * STAGE_BYTES;
#pragma unroll
        for (int kt = 0; kt < 4; ++kt) {
            uint32_t csw = (uint32_t)((kt * 2 + lhalf) ^ lxor) * 16;
            uint32_t bf[2][4];
            LDMX4(bf[0], w_row + so + csw);
            LDMX4(bf[1], w_row + so + 16 * 128 + csw);
#pragma unroll
            for (int mt = 0; mt < 4; ++mt) {
                uint32_t af[4];
                LDMX4(af, a_row + so + mt * 16 * 128 + csw);
#pragma unroll
                for (int nt = 0; nt < 4; ++nt)
                    MMA16816(acc[mt][nt], af, bf[nt >> 1][nt & 1], bf[nt >> 1][(nt & 1) + 2]);
            }
        }
    };

    // ---- 3-stage pipeline ----
    issue_chunk(0, 0);
    issue_chunk(1, 1);
    cp_wait<1>();
    __syncthreads();

    int si = 0;
#pragma unroll 1
    for (int kc = 0; kc < NCH; ++kc) {
        if (kc + 2 < NCH) {
            int st = si + 2; if (st >= NSTAGE) st -= NSTAGE;
            issue_chunk(kc + 2, st);
        }
        do_mma(si);
        if (kc + 2 < NCH) cp_wait<1>(); else cp_wait<0>();
        __syncthreads();
        if (++si == NSTAGE) si = 0;
    }

    // ---- fused epilogue: bias -> hardtanh -> mish -> GroupNorm (group == 128 ch) ----
    float ps[4][2], pq[4][2];
#pragma unroll
    for (int mt = 0; mt < 4; ++mt)
#pragma unroll
        for (int rr = 0; rr < 2; ++rr) { ps[mt][rr] = 0.f; pq[mt][rr] = 0.f; }

#pragma unroll
    for (int mt = 0; mt < 4; ++mt)
#pragma unroll
        for (int nt = 0; nt < 4; ++nt)
#pragma unroll
            for (int rr = 0; rr < 2; ++rr)
#pragma unroll
                for (int j = 0; j < 2; ++j) {
                    int n = wn * 32 + nt * 8 + (lane & 3) * 2 + j;
                    float y = acc[mt][nt][rr * 2 + j] + bs[n];
                    y = fminf(1.0f, fmaxf(-1.0f, y));        // hardtanh
                    float z = 1.0f + __expf(y);              // mish: y*(z^2-1)/(z^2+1)
                    float z2 = z * z;
                    float m = y * __fdividef(z2 - 1.0f, z2 + 1.0f);
                    acc[mt][nt][rr * 2 + j] = m;
                    ps[mt][rr] += m;
                    pq[mt][rr] = fmaf(m, m, pq[mt][rr]);
                }

#pragma unroll
    for (int mt = 0; mt < 4; ++mt)
#pragma unroll
        for (int rr = 0; rr < 2; ++rr) {
            float s = ps[mt][rr], q = pq[mt][rr];
            s += __shfl_xor_sync(0xFFFFFFFFu, s, 1);
            q += __shfl_xor_sync(0xFFFFFFFFu, q, 1);
            s += __shfl_xor_sync(0xFFFFFFFFu, s, 2);
            q += __shfl_xor_sync(0xFFFFFFFFu, q, 2);
            if ((lane & 3) == 0) {
                int row = wm * 64 + mt * 16 + (lane >> 2) + rr * 8;
                red[row * 4 + wn] = make_float2(s, q);
            }
        }
    __syncthreads();

#pragma unroll
    for (int mt = 0; mt < 4; ++mt)
#pragma unroll
        for (int rr = 0; rr < 2; ++rr) {
            int row = wm * 64 + mt * 16 + (lane >> 2) + rr * 8;
            float2 r0 = red[row * 4 + 0], r1 = red[row * 4 + 1];
            float2 r2 = red[row * 4 + 2], r3 = red[row * 4 + 3];
            float s = r0.x + r1.x + r2.x + r3.x;
            float q = r0.y + r1.y + r2.y + r3.y;
            float mean = s * 0.0078125f;
            float var  = fmaf(-mean, mean, q * 0.0078125f);
            float rs   = rsqrtf(var + 1e-5f);
            float* orow = out + (size_t)(m0 + row) * NDIM + n0;
#pragma unroll
            for (int nt = 0; nt < 4; ++nt) {
                int n = wn * 32 + nt * 8 + (lane & 3) * 2;
                float2 o;
                o.x = fmaf((acc[mt][nt][rr * 2 + 0] - mean) * rs, gws[n + 0], gbs[n + 0]);
                o.y = fmaf((acc[mt][nt][rr * 2 + 1] - mean) * rs, gws[n + 1], gbs[n + 1]);
                *(float2*)(orow + n) = o;
            }
        }
}

// ---------------- launch ----------------
extern "C" void kernel_launch(void* const* d_in, const int* in_sizes, int n_in,
                              void* d_out, int out_size) {
    const float* x  = (const float*)d_in[0];
    const float* w  = (const float*)d_in[1];
    const float* bl = (const float*)d_in[2];
    const float* be = (const float*)d_in[3];
    const float* gw = (const float*)d_in[4];
    const float* gb = (const float*)d_in[5];
    float* out = (float*)d_out;

    static __half* xh_p = nullptr;
    static __half* wh_p = nullptr;
    if (!xh_p) {
        cudaGetSymbolAddress((void**)&xh_p, g_xh);
        cudaGetSymbolAddress((void**)&wh_p, g_wh);
        cudaFuncSetAttribute(fused_gemm_mish_gn,
                             cudaFuncAttributeMaxDynamicSharedMemorySize, SMEM_BYTES);
    }

    cvt2_kernel<<<XBLK + WBLK, 256>>>(x, w, xh_p, wh_p);

    dim3 grid(NDIM / 128, BDIM / 128);   // (32, 64)
    fused_gemm_mish_gn<<<grid, 256, SMEM_BYTES>>>(bl, be, gw, gb, out);
}

// round 13
// speedup vs baseline: 1.2263x; 1.2263x over previous
#include <cuda_runtime.h>
#include <cuda_fp16.h>
#include <cstdint>

static constexpr int KDIM = 4096;
static constexpr int NDIM = 4096;
static constexpr int BDIM = 8192;
static constexpr int BK   = 64;
static constexpr int STAGE_A = 0;
static constexpr int STAGE_W = 16384;
static constexpr int STAGE_BYTES = 32768;
static constexpr int OFF_BS  = 3 * STAGE_BYTES;        // 98304
static constexpr int OFF_GW  = OFF_BS + 512;
static constexpr int OFF_GB  = OFF_GW + 512;
static constexpr int OFF_RED = OFF_GB + 512;           // float2[128][4] = 4096
static constexpr int OFF_MB  = OFF_RED + 4096;         // 6 mbarriers (48B)
static constexpr int SMEM_BYTES = OFF_MB + 64;         // 104512 -> 2 CTAs/SM

__device__ __align__(16) __half g_xh[(size_t)BDIM * KDIM];   // 64 MB
__device__ __align__(16) __half g_wh[(size_t)NDIM * KDIM];   // 32 MB

#define DINL __device__ __forceinline__

DINL uint32_t smem_u32(const void* p) {
    uint32_t a;
    asm("{ .reg .u64 t; cvta.to.shared.u64 t, %1; cvt.u32.u64 %0, t; }" : "=r"(a) : "l"(p));
    return a;
}
DINL void cp_async16(uint32_t s, const void* g) {
    asm volatile("cp.async.cg.shared.global [%0], [%1], 16;" :: "r"(s), "l"(g) : "memory");
}

#define MB_INIT(ADDR, CNT)                                                          \
    asm volatile("mbarrier.init.shared::cta.b64 [%0], %1;" :: "r"(ADDR), "r"(CNT) : "memory")

// arrive on mbarrier when this thread's prior cp.asyncs complete (no count inc)
#define CP_MBAR(ADDR)                                                               \
    asm volatile("cp.async.mbarrier.arrive.noinc.shared::cta.b64 [%0];" :: "r"(ADDR) : "memory")

#define MARRIVE(ADDR)                                                               \
    asm volatile("{.reg .b64 t; mbarrier.arrive.shared::cta.b64 t, [%0];}" :: "r"(ADDR) : "memory")

#define MWAIT(ADDR, PH) do {                                                        \
    uint32_t _done;                                                                 \
    do {                                                                            \
        asm volatile("{.reg .pred p; "                                              \
            "mbarrier.try_wait.parity.shared::cta.b64 p, [%1], %2; "                \
            "selp.b32 %0, 1, 0, p;}"                                                \
            : "=r"(_done) : "r"(ADDR), "r"((uint32_t)(PH)) : "memory");             \
    } while (!_done);                                                               \
} while (0)

#define LDMX4(d, addr)                                                              \
    asm volatile("ldmatrix.sync.aligned.m8n8.x4.shared.b16 {%0,%1,%2,%3}, [%4];"    \
        : "=r"((d)[0]), "=r"((d)[1]), "=r"((d)[2]), "=r"((d)[3]) : "r"(addr))

#define MMA16816(c, a, b0, b1)                                                      \
    asm volatile("mma.sync.aligned.m16n8k16.row.col.f32.f16.f16.f32 "               \
        "{%0,%1,%2,%3}, {%4,%5,%6,%7}, {%8,%9}, {%0,%1,%2,%3};"                     \
        : "+f"((c)[0]), "+f"((c)[1]), "+f"((c)[2]), "+f"((c)[3])                    \
        : "r"((a)[0]), "r"((a)[1]), "r"((a)[2]), "r"((a)[3]), "r"(b0), "r"(b1))

// ---------------- fp32 -> fp16 pre-convert (both tensors, one launch) ----------------
static constexpr int XBLK = (int)((size_t)BDIM * KDIM / 2048);   // 16384
static constexpr int WBLK = (int)((size_t)NDIM * KDIM / 2048);   // 8192

__global__ void __launch_bounds__(256) cvt2_kernel(const float* __restrict__ x,
                                                   const float* __restrict__ w,
                                                   __half* __restrict__ xh,
                                                   __half* __restrict__ wh) {
    int b = blockIdx.x;
    const float* src; __half* dst;
    size_t base;
    if (b < XBLK) { src = x; dst = xh; base = (size_t)b * 2048; }
    else          { src = w; dst = wh; base = (size_t)(b - XBLK) * 2048; }
    size_t i = base + (size_t)threadIdx.x * 8;
    float4 f0 = *(const float4*)(src + i);
    float4 f1 = *(const float4*)(src + i + 4);
    __half2 h0 = __floats2half2_rn(f0.x, f0.y);
    __half2 h1 = __floats2half2_rn(f0.z, f0.w);
    __half2 h2 = __floats2half2_rn(f1.x, f1.y);
    __half2 h3 = __floats2half2_rn(f1.z, f1.w);
    uint4 v = {*(uint32_t*)&h0, *(uint32_t*)&h1, *(uint32_t*)&h2, *(uint32_t*)&h3};
    *(uint4*)(dst + i) = v;
}

// ---------------- fused GEMM + bias + hardtanh + mish + GroupNorm ----------------
__global__ void __launch_bounds__(512, 2)
fused_gemm_mish_gn(const float* __restrict__ bl, const float* __restrict__ be,
                   const float* __restrict__ gwp, const float* __restrict__ gbp,
                   float* __restrict__ out) {
    extern __shared__ __align__(16) unsigned char sm[];
    const uint32_t sb = smem_u32(sm);

    const int tid  = threadIdx.x;
    const int lane = tid & 31;
    const int wid  = tid >> 5;         // 16 warps
    const int wn   = wid & 3;          // 4 col-blocks of 32
    const int wm   = wid >> 2;         // 4 row-blocks of 32
    const int m0   = blockIdx.y << 7;
    const int n0   = blockIdx.x << 7;

    float* bs  = (float*)(sm + OFF_BS);
    float* gws = (float*)(sm + OFF_GW);
    float* gbs = (float*)(sm + OFF_GB);
    float2* red = (float2*)(sm + OFF_RED);
    const uint32_t fb = sb + OFF_MB;        // full[0..2] at +0,+8,+16
    const uint32_t eb = sb + OFF_MB + 24;   // empty[0..2] at +0,+8,+16

    if (tid == 0) {
#pragma unroll
        for (int s = 0; s < 3; ++s) { MB_INIT(fb + s * 8, 512u); MB_INIT(eb + s * 8, 512u); }
    }
    if (tid < 128) {
        bs[tid]  = bl[n0 + tid] + be[n0 + tid];
        gws[tid] = gwp[n0 + tid];
        gbs[tid] = gbp[n0 + tid];
    }
    __syncthreads();

    // ---- cp.async mapping: thread t -> row (t>>2), two 16B chunks (t&3)*2+{0,1} ----
    const int ld_row = tid >> 2;
    const int ld_cb  = (tid & 3) * 2;
    const uint32_t swz0 = (uint32_t)(ld_cb ^ (ld_row & 7)) * 16;
    const uint32_t swz1 = (uint32_t)((ld_cb + 1) ^ (ld_row & 7)) * 16;
    const __half* ga = g_xh + (size_t)(m0 + ld_row) * KDIM + ld_cb * 8;
    const __half* gw = g_wh + (size_t)(n0 + ld_row) * KDIM + ld_cb * 8;
    const uint32_t sts_a = sb + STAGE_A + (uint32_t)ld_row * 128;
    const uint32_t sts_w = sb + STAGE_W + (uint32_t)ld_row * 128;

    // issue chunk at half-offset koff*64 from (ga,gw) into stage byte-offset so
    auto issue = [&](int koff, uint32_t so) {
        const __half* a = ga + koff * 64;
        const __half* w = gw + koff * 64;
        cp_async16(sts_a + so + swz0, a);
        cp_async16(sts_a + so + swz1, a + 8);
        cp_async16(sts_w + so + swz0, w);
        cp_async16(sts_w + so + swz1, w + 8);
    };

    float acc[2][4][4];
#pragma unroll
    for (int i = 0; i < 2; ++i)
#pragma unroll
        for (int j = 0; j < 4; ++j)
#pragma unroll
            for (int k = 0; k < 4; ++k) acc[i][j][k] = 0.f;

    const uint32_t a_row = sb + STAGE_A + (uint32_t)(wm * 32 + (lane & 15)) * 128;
    const uint32_t w_row = sb + STAGE_W + (uint32_t)(wn * 32 + (lane & 15)) * 128;
    const int lhalf = lane >> 4;
    const int lxor  = lane & 7;

    auto do_mma = [&](uint32_t so) {
#pragma unroll
        for (int kt = 0; kt < 4; ++kt) {
            uint32_t csw = (uint32_t)((kt * 2 + lhalf) ^ lxor) * 16;
            uint32_t af[2][4], bf[2][4];
            LDMX4(af[0], a_row + so + csw);
            LDMX4(af[1], a_row + so + 16 * 128 + csw);
            LDMX4(bf[0], w_row + so + csw);
            LDMX4(bf[1], w_row + so + 16 * 128 + csw);
#pragma unroll
            for (int mt = 0; mt < 2; ++mt)
#pragma unroll
                for (int nt = 0; nt < 4; ++nt)
                    MMA16816(acc[mt][nt], af[mt], bf[nt >> 1][nt & 1], bf[nt >> 1][(nt & 1) + 2]);
        }
    };

    // ---- prologue: chunks 0 -> stage 0, 1 -> stage 1 ----
    issue(0, 0);         CP_MBAR(fb + 0);
    issue(1, 32768);     CP_MBAR(fb + 8);

    // ---- steady state: 6-chunk blocks; all stage/parity constants static ----
    // step i: produce chunk b+i+2 into stage (i+2)%3 (empty-wait parity per schedule),
    //         consume chunk b+i from stage i%3 (full parity 0,0,0,1,1,1)
#define BLOCK6(FIRST)                                                               \
    do {                                                                            \
        if (!(FIRST)) MWAIT(eb + 16, 1);                                            \
        issue(2, 65536); CP_MBAR(fb + 16);                                          \
        MWAIT(fb + 0, 0);  do_mma(0);      MARRIVE(eb + 0);                         \
        MWAIT(eb + 0, 0);                                                           \
        issue(3, 0);     CP_MBAR(fb + 0);                                           \
        MWAIT(fb + 8, 0);  do_mma(32768);  MARRIVE(eb + 8);                         \
        MWAIT(eb + 8, 0);                                                           \
        issue(4, 32768); CP_MBAR(fb + 8);                                           \
        MWAIT(fb + 16, 0); do_mma(65536);  MARRIVE(eb + 16);                        \
        MWAIT(eb + 16, 0);                                                          \
        issue(5, 65536); CP_MBAR(fb + 16);                                          \
        MWAIT(fb + 0, 1);  do_mma(0);      MARRIVE(eb + 0);                         \
        MWAIT(eb + 0, 1);                                                           \
        issue(6, 0);     CP_MBAR(fb + 0);                                           \
        MWAIT(fb + 8, 1);  do_mma(32768);  MARRIVE(eb + 8);                         \
        MWAIT(eb + 8, 1);                                                           \
        issue(7, 32768); CP_MBAR(fb + 8);                                           \
        MWAIT(fb + 16, 1); do_mma(65536);  MARRIVE(eb + 16);                        \
        ga += 6 * 64; gw += 6 * 64;                                                 \
    } while (0)

    BLOCK6(true);
#pragma unroll 1
    for (int j = 1; j < 10; ++j) BLOCK6(false);

    // ---- tail: chunks 60..63 (ga at chunk 60) ----
    MWAIT(eb + 16, 1);
    issue(2, 65536); CP_MBAR(fb + 16);               // chunk 62 -> stage 2
    MWAIT(fb + 0, 0);  do_mma(0);     MARRIVE(eb + 0);    // chunk 60
    MWAIT(eb + 0, 0);
    issue(3, 0);     CP_MBAR(fb + 0);                // chunk 63 -> stage 0
    MWAIT(fb + 8, 0);  do_mma(32768);                 // chunk 61
    MWAIT(fb + 16, 0); do_mma(65536);                 // chunk 62
    MWAIT(fb + 0, 1);  do_mma(0);                     // chunk 63

    // ---- fused epilogue: bias -> hardtanh -> mish -> GroupNorm (group == 128 ch) ----
    float ps[2][2], pq[2][2];
#pragma unroll
    for (int mt = 0; mt < 2; ++mt)
#pragma unroll
        for (int rr = 0; rr < 2; ++rr) { ps[mt][rr] = 0.f; pq[mt][rr] = 0.f; }

#pragma unroll
    for (int mt = 0; mt < 2; ++mt)
#pragma unroll
        for (int nt = 0; nt < 4; ++nt)
#pragma unroll
            for (int rr = 0; rr < 2; ++rr)
#pragma unroll
                for (int j = 0; j < 2; ++j) {
                    int n = wn * 32 + nt * 8 + (lane & 3) * 2 + j;
                    float y = acc[mt][nt][rr * 2 + j] + bs[n];
                    y = fminf(1.0f, fmaxf(-1.0f, y));        // hardtanh
                    float z = 1.0f + __expf(y);              // mish: y*(z^2-1)/(z^2+1)
                    float z2 = z * z;
                    float m = y * __fdividef(z2 - 1.0f, z2 + 1.0f);
                    acc[mt][nt][rr * 2 + j] = m;
                    ps[mt][rr] += m;
                    pq[mt][rr] = fmaf(m, m, pq[mt][rr]);
                }

#pragma unroll
    for (int mt = 0; mt < 2; ++mt)
#pragma unroll
        for (int rr = 0; rr < 2; ++rr) {
            float s = ps[mt][rr], q = pq[mt][rr];
            s += __shfl_xor_sync(0xFFFFFFFFu, s, 1);
            q += __shfl_xor_sync(0xFFFFFFFFu, q, 1);
            s += __shfl_xor_sync(0xFFFFFFFFu, s, 2);
            q += __shfl_xor_sync(0xFFFFFFFFu, q, 2);
            if ((lane & 3) == 0) {
                int row = wm * 32 + mt * 16 + (lane >> 2) + rr * 8;
                red[row * 4 + wn] = make_float2(s, q);
            }
        }
    __syncthreads();

#pragma unroll
    for (int mt = 0; mt < 2; ++mt)
#pragma unroll
        for (int rr = 0; rr < 2; ++rr) {
            int row = wm * 32 + mt * 16 + (lane >> 2) + rr * 8;
            float2 r0 = red[row * 4 + 0], r1 = red[row * 4 + 1];
            float2 r2 = red[row * 4 + 2], r3 = red[row * 4 + 3];
            float s = r0.x + r1.x + r2.x + r3.x;
            float q = r0.y + r1.y + r2.y + r3.y;
            float mean = s * 0.0078125f;
            float var  = fmaf(-mean, mean, q * 0.0078125f);
            float rs   = rsqrtf(var + 1e-5f);
            float* orow = out + (size_t)(m0 + row) * NDIM + n0;
#pragma unroll
            for (int nt = 0; nt < 4; ++nt) {
                int n = wn * 32 + nt * 8 + (lane & 3) * 2;
                float2 o;
                o.x = fmaf((acc[mt][nt][rr * 2 + 0] - mean) * rs, gws[n + 0], gbs[n + 0]);
                o.y = fmaf((acc[mt][nt][rr * 2 + 1] - mean) * rs, gws[n + 1], gbs[n + 1]);
                *(float2*)(orow + n) = o;
            }
        }
}

// ---------------- launch ----------------
extern "C" void kernel_launch(void* const* d_in, const int* in_sizes, int n_in,
                              void* d_out, int out_size) {
    const float* x  = (const float*)d_in[0];
    const float* w  = (const float*)d_in[1];
    const float* bl = (const float*)d_in[2];
    const float* be = (const float*)d_in[3];
    const float* gw = (const float*)d_in[4];
    const float* gb = (const float*)d_in[5];
    float* out = (float*)d_out;

    static __half* xh_p = nullptr;
    static __half* wh_p = nullptr;
    if (!xh_p) {
        cudaGetSymbolAddress((void**)&xh_p, g_xh);
        cudaGetSymbolAddress((void**)&wh_p, g_wh);
        cudaFuncSetAttribute(fused_gemm_mish_gn,
                             cudaFuncAttributeMaxDynamicSharedMemorySize, SMEM_BYTES);
    }

    cvt2_kernel<<<XBLK + WBLK, 256>>>(x, w, xh_p, wh_p);

    dim3 grid(NDIM / 128, BDIM / 128);   // (32, 64)
    fused_gemm_mish_gn<<<grid, 512, SMEM_BYTES>>>(bl, be, gw, gb, out);
}

// round 14
// speedup vs baseline: 1.2279x; 1.0013x over previous
#include <cuda_runtime.h>
#include <cuda_fp16.h>
#include <cstdint>

static constexpr int KDIM = 4096;
static constexpr int NDIM = 4096;
static constexpr int BDIM = 8192;
static constexpr int BK   = 64;
static constexpr int STAGE_A = 0;
static constexpr int STAGE_W = 16384;
static constexpr int STAGE_BYTES = 32768;
static constexpr int OFF_BS  = 3 * STAGE_BYTES;        // 98304
static constexpr int OFF_GW  = OFF_BS + 512;
static constexpr int OFF_GB  = OFF_GW + 512;
static constexpr int OFF_RED = OFF_GB + 512;           // float2[128][4] = 4096
static constexpr int OFF_MB  = OFF_RED + 4096;         // 6 mbarriers (48B)
static constexpr int SMEM_BYTES = OFF_MB + 64;         // 104512 -> 2 CTAs/SM

__device__ __align__(16) __half g_xh[(size_t)BDIM * KDIM];   // 64 MB
__device__ __align__(16) __half g_wh[(size_t)NDIM * KDIM];   // 32 MB

#define DINL __device__ __forceinline__

DINL uint32_t smem_u32(const void* p) {
    uint32_t a;
    asm("{ .reg .u64 t; cvta.to.shared.u64 t, %1; cvt.u32.u64 %0, t; }" : "=r"(a) : "l"(p));
    return a;
}
DINL void cp_async16(uint32_t s, const void* g) {
    asm volatile("cp.async.cg.shared.global [%0], [%1], 16;" :: "r"(s), "l"(g) : "memory");
}

#define MB_INIT(ADDR, CNT)                                                          \
    asm volatile("mbarrier.init.shared::cta.b64 [%0], %1;" :: "r"(ADDR), "r"(CNT) : "memory")

#define CP_MBAR(ADDR)                                                               \
    asm volatile("cp.async.mbarrier.arrive.noinc.shared::cta.b64 [%0];" :: "r"(ADDR) : "memory")

#define MARRIVE(ADDR)                                                               \
    asm volatile("{.reg .b64 t; mbarrier.arrive.shared::cta.b64 t, [%0];}" :: "r"(ADDR) : "memory")

#define MWAIT(ADDR, PH) do {                                                        \
    uint32_t _done;                                                                 \
    do {                                                                            \
        asm volatile("{.reg .pred p; "                                              \
            "mbarrier.try_wait.parity.shared::cta.b64 p, [%1], %2; "                \
            "selp.b32 %0, 1, 0, p;}"                                                \
            : "=r"(_done) : "r"(ADDR), "r"((uint32_t)(PH)) : "memory");             \
    } while (!_done);                                                               \
} while (0)

#define LDMX4(d, addr)                                                              \
    asm volatile("ldmatrix.sync.aligned.m8n8.x4.shared.b16 {%0,%1,%2,%3}, [%4];"    \
        : "=r"((d)[0]), "=r"((d)[1]), "=r"((d)[2]), "=r"((d)[3]) : "r"(addr))

#define MMA16816(c, a, b0, b1)                                                      \
    asm volatile("mma.sync.aligned.m16n8k16.row.col.f32.f16.f16.f32 "               \
        "{%0,%1,%2,%3}, {%4,%5,%6,%7}, {%8,%9}, {%0,%1,%2,%3};"                     \
        : "+f"((c)[0]), "+f"((c)[1]), "+f"((c)[2]), "+f"((c)[3])                    \
        : "r"((a)[0]), "r"((a)[1]), "r"((a)[2]), "r"((a)[3]), "r"(b0), "r"(b1))

// ---------------- fp32 -> fp16 pre-convert (both tensors, one launch) ----------------
static constexpr int XBLK = (int)((size_t)BDIM * KDIM / 2048);   // 16384
static constexpr int WBLK = (int)((size_t)NDIM * KDIM / 2048);   // 8192

__global__ void __launch_bounds__(256) cvt2_kernel(const float* __restrict__ x,
                                                   const float* __restrict__ w,
                                                   __half* __restrict__ xh,
                                                   __half* __restrict__ wh) {
    int b = blockIdx.x;
    const float* src; __half* dst;
    size_t base;
    if (b < XBLK) { src = x; dst = xh; base = (size_t)b * 2048; }
    else          { src = w; dst = wh; base = (size_t)(b - XBLK) * 2048; }
    size_t i = base + (size_t)threadIdx.x * 8;
    float4 f0 = *(const float4*)(src + i);
    float4 f1 = *(const float4*)(src + i + 4);
    __half2 h0 = __floats2half2_rn(f0.x, f0.y);
    __half2 h1 = __floats2half2_rn(f0.z, f0.w);
    __half2 h2 = __floats2half2_rn(f1.x, f1.y);
    __half2 h3 = __floats2half2_rn(f1.z, f1.w);
    uint4 v = {*(uint32_t*)&h0, *(uint32_t*)&h1, *(uint32_t*)&h2, *(uint32_t*)&h3};
    *(uint4*)(dst + i) = v;
}

// ---------------- fused GEMM + bias + hardtanh + mish + GroupNorm ----------------
__global__ void __launch_bounds__(512, 2)
fused_gemm_mish_gn(const float* __restrict__ bl, const float* __restrict__ be,
                   const float* __restrict__ gwp, const float* __restrict__ gbp,
                   float* __restrict__ out) {
    extern __shared__ __align__(16) unsigned char sm[];
    const uint32_t sb = smem_u32(sm);

    const int tid  = threadIdx.x;
    const int lane = tid & 31;
    const int wid  = tid >> 5;         // 16 warps
    const int wn   = wid & 3;          // 4 col-blocks of 32
    const int wm   = wid >> 2;         // 4 row-blocks of 32
    const int m0   = blockIdx.y << 7;
    const int n0   = blockIdx.x << 7;

    float* bs  = (float*)(sm + OFF_BS);
    float* gws = (float*)(sm + OFF_GW);
    float* gbs = (float*)(sm + OFF_GB);
    float2* red = (float2*)(sm + OFF_RED);
    const uint32_t fb = sb + OFF_MB;        // full[0..2] at +0,+8,+16
    const uint32_t eb = sb + OFF_MB + 24;   // empty[0..2] at +0,+8,+16

    if (tid == 0) {
#pragma unroll
        for (int s = 0; s < 3; ++s) { MB_INIT(fb + s * 8, 512u); MB_INIT(eb + s * 8, 512u); }
    }
    if (tid < 128) {
        bs[tid]  = bl[n0 + tid] + be[n0 + tid];
        gws[tid] = gwp[n0 + tid];
        gbs[tid] = gbp[n0 + tid];
    }
    __syncthreads();
    // pre-complete phase 0 of all EMPTY barriers so the first empty-waits pass
    MARRIVE(eb + 0); MARRIVE(eb + 8); MARRIVE(eb + 16);

    // ---- cp.async mapping: thread t -> row (t>>2), two 16B chunks (t&3)*2+{0,1} ----
    const int ld_row = tid >> 2;
    const int ld_cb  = (tid & 3) * 2;
    const uint32_t swz0 = (uint32_t)(ld_cb ^ (ld_row & 7)) * 16;
    const uint32_t swz1 = (uint32_t)((ld_cb + 1) ^ (ld_row & 7)) * 16;
    const __half* ga = g_xh + (size_t)(m0 + ld_row) * KDIM + ld_cb * 8;
    const __half* gw = g_wh + (size_t)(n0 + ld_row) * KDIM + ld_cb * 8;
    const uint32_t sts_a = sb + STAGE_A + (uint32_t)ld_row * 128;
    const uint32_t sts_w = sb + STAGE_W + (uint32_t)ld_row * 128;

    auto issue = [&](int koff, uint32_t so) {
        const __half* a = ga + koff * 64;
        const __half* w = gw + koff * 64;
        cp_async16(sts_a + so + swz0, a);
        cp_async16(sts_a + so + swz1, a + 8);
        cp_async16(sts_w + so + swz0, w);
        cp_async16(sts_w + so + swz1, w + 8);
    };

    float acc[2][4][4];
#pragma unroll
    for (int i = 0; i < 2; ++i)
#pragma unroll
        for (int j = 0; j < 4; ++j)
#pragma unroll
            for (int k = 0; k < 4; ++k) acc[i][j][k] = 0.f;

    const uint32_t a_row = sb + STAGE_A + (uint32_t)(wm * 32 + (lane & 15)) * 128;
    const uint32_t w_row = sb + STAGE_W + (uint32_t)(wn * 32 + (lane & 15)) * 128;
    const int lhalf = lane >> 4;
    const int lxor  = lane & 7;

    auto do_mma = [&](uint32_t so) {
#pragma unroll
        for (int kt = 0; kt < 4; ++kt) {
            uint32_t csw = (uint32_t)((kt * 2 + lhalf) ^ lxor) * 16;
            uint32_t af[2][4], bf[2][4];
            LDMX4(af[0], a_row + so + csw);
            LDMX4(af[1], a_row + so + 16 * 128 + csw);
            LDMX4(bf[0], w_row + so + csw);
            LDMX4(bf[1], w_row + so + 16 * 128 + csw);
#pragma unroll
            for (int mt = 0; mt < 2; ++mt)
#pragma unroll
                for (int nt = 0; nt < 4; ++nt)
                    MMA16816(acc[mt][nt], af[mt], bf[nt >> 1][nt & 1], bf[nt >> 1][(nt & 1) + 2]);
        }
    };

    // ---- prologue: chunk 0 -> stage 0, chunk 1 -> stage 1 (2-chunk lead) ----
    issue(0, 0);       CP_MBAR(fb + 0);
    issue(1, 32768);   CP_MBAR(fb + 8);

    // ---- steady state: issue k+2 (waiting on stage consumed at k-1), then mma k ----
#define BLOCK6()                                                                    \
    do {                                                                            \
        MWAIT(eb + 16, 0); issue(2, 65536); CP_MBAR(fb + 16);                       \
        MWAIT(fb + 0, 0);  do_mma(0);      MARRIVE(eb + 0);                         \
        MWAIT(eb + 0, 1);  issue(3, 0);     CP_MBAR(fb + 0);                        \
        MWAIT(fb + 8, 0);  do_mma(32768);  MARRIVE(eb + 8);                         \
        MWAIT(eb + 8, 1);  issue(4, 32768); CP_MBAR(fb + 8);                        \
        MWAIT(fb + 16, 0); do_mma(65536);  MARRIVE(eb + 16);                        \
        MWAIT(eb + 16, 1); issue(5, 65536); CP_MBAR(fb + 16);                       \
        MWAIT(fb + 0, 1);  do_mma(0);      MARRIVE(eb + 0);                         \
        MWAIT(eb + 0, 0);  issue(6, 0);     CP_MBAR(fb + 0);                        \
        MWAIT(fb + 8, 1);  do_mma(32768);  MARRIVE(eb + 8);                         \
        MWAIT(eb + 8, 0);  issue(7, 32768); CP_MBAR(fb + 8);                        \
        MWAIT(fb + 16, 1); do_mma(65536);  MARRIVE(eb + 16);                        \
        ga += 6 * 64; gw += 6 * 64;                                                 \
    } while (0)

#pragma unroll 1
    for (int j = 0; j < 10; ++j) BLOCK6();

    // ---- tail: chunks 60..63 (ga at chunk 60) ----
    MWAIT(eb + 16, 0); issue(2, 65536); CP_MBAR(fb + 16);   // chunk 62 -> stage 2
    MWAIT(fb + 0, 0);  do_mma(0);      MARRIVE(eb + 0);      // chunk 60
    MWAIT(eb + 0, 1);  issue(3, 0);     CP_MBAR(fb + 0);     // chunk 63 -> stage 0
    MWAIT(fb + 8, 0);  do_mma(32768);                        // chunk 61
    MWAIT(fb + 16, 0); do_mma(65536);                        // chunk 62
    MWAIT(fb + 0, 1);  do_mma(0);                            // chunk 63

    // ---- fused epilogue: bias -> hardtanh -> mish -> GroupNorm (group == 128 ch) ----
    float ps[2][2], pq[2][2];
#pragma unroll
    for (int mt = 0; mt < 2; ++mt)
#pragma unroll
        for (int rr = 0; rr < 2; ++rr) { ps[mt][rr] = 0.f; pq[mt][rr] = 0.f; }

#pragma unroll
    for (int mt = 0; mt < 2; ++mt)
#pragma unroll
        for (int nt = 0; nt < 4; ++nt)
#pragma unroll
            for (int rr = 0; rr < 2; ++rr)
#pragma unroll
                for (int j = 0; j < 2; ++j) {
                    int n = wn * 32 + nt * 8 + (lane & 3) * 2 + j;
                    float y = acc[mt][nt][rr * 2 + j] + bs[n];
                    y = fminf(1.0f, fmaxf(-1.0f, y));        // hardtanh
                    float z = 1.0f + __expf(y);              // mish: y*(z^2-1)/(z^2+1)
                    float z2 = z * z;
                    float m = y * __fdividef(z2 - 1.0f, z2 + 1.0f);
                    acc[mt][nt][rr * 2 + j] = m;
                    ps[mt][rr] += m;
                    pq[mt][rr] = fmaf(m, m, pq[mt][rr]);
                }

#pragma unroll
    for (int mt = 0; mt < 2; ++mt)
#pragma unroll
        for (int rr = 0; rr < 2; ++rr) {
            float s = ps[mt][rr], q = pq[mt][rr];
            s += __shfl_xor_sync(0xFFFFFFFFu, s, 1);
            q += __shfl_xor_sync(0xFFFFFFFFu, q, 1);
            s += __shfl_xor_sync(0xFFFFFFFFu, s, 2);
            q += __shfl_xor_sync(0xFFFFFFFFu, q, 2);
            if ((lane & 3) == 0) {
                int row = wm * 32 + mt * 16 + (lane >> 2) + rr * 8;
                red[row * 4 + wn] = make_float2(s, q);
            }
        }
    __syncthreads();

#pragma unroll
    for (int mt = 0; mt < 2; ++mt)
#pragma unroll
        for (int rr = 0; rr < 2; ++rr) {
            int row = wm * 32 + mt * 16 + (lane >> 2) + rr * 8;
            float2 r0 = red[row * 4 + 0], r1 = red[row * 4 + 1];
            float2 r2 = red[row * 4 + 2], r3 = red[row * 4 + 3];
            float s = r0.x + r1.x + r2.x + r3.x;
            float q = r0.y + r1.y + r2.y + r3.y;
            float mean = s * 0.0078125f;
            float var  = fmaf(-mean, mean, q * 0.0078125f);
            float rs   = rsqrtf(var + 1e-5f);
            float* orow = out + (size_t)(m0 + row) * NDIM + n0;
#pragma unroll
            for (int nt = 0; nt < 4; ++nt) {
                int n = wn * 32 + nt * 8 + (lane & 3) * 2;
                float2 o;
                o.x = fmaf((acc[mt][nt][rr * 2 + 0] - mean) * rs, gws[n + 0], gbs[n + 0]);
                o.y = fmaf((acc[mt][nt][rr * 2 + 1] - mean) * rs, gws[n + 1], gbs[n + 1]);
                *(float2*)(orow + n) = o;
            }
        }
}

// ---------------- launch ----------------
extern "C" void kernel_launch(void* const* d_in, const int* in_sizes, int n_in,
                              void* d_out, int out_size) {
    const float* x  = (const float*)d_in[0];
    const float* w  = (const float*)d_in[1];
    const float* bl = (const float*)d_in[2];
    const float* be = (const float*)d_in[3];
    const float* gw = (const float*)d_in[4];
    const float* gb = (const float*)d_in[5];
    float* out = (float*)d_out;

    static __half* xh_p = nullptr;
    static __half* wh_p = nullptr;
    if (!xh_p) {
        cudaGetSymbolAddress((void**)&xh_p, g_xh);
        cudaGetSymbolAddress((void**)&wh_p, g_wh);
        cudaFuncSetAttribute(fused_gemm_mish_gn,
                             cudaFuncAttributeMaxDynamicSharedMemorySize, SMEM_BYTES);
    }

    cvt2_kernel<<<XBLK + WBLK, 256>>>(x, w, xh_p, wh_p);

    dim3 grid(NDIM / 128, BDIM / 128);   // (32, 64)
    fused_gemm_mish_gn<<<grid, 512, SMEM_BYTES>>>(bl, be, gw, gb, out);
}